// round 3
// baseline (speedup 1.0000x reference)
#include <cuda_runtime.h>
#include <cstddef>

#define BATCH   8
#define NPTS    8192
#define CFEAT   32
#define NPOINT  1024
#define NSAMPLE 32
#define OUTC    35            // 3 (centered xyz) + 32 (features)
#define R2      0.0625f       // 0.25^2, exact in fp32

typedef unsigned long long u64;

// Spatially sorted copies of xyz (per batch) + original indices.
__device__ float d_sx[BATCH * NPTS];
__device__ float d_sy[BATCH * NPTS];
__device__ float d_sz[BATCH * NPTS];
__device__ int   d_sorig[BATCH * NPTS];

// 4-bit Morton spread: bit k of input -> bit 3k of output.
__constant__ unsigned short MORT4[16] = {
    0, 1, 8, 9, 64, 65, 72, 73, 512, 513, 520, 521, 576, 577, 584, 585
};

// ---------------------------------------------------------------------------
// Warp redux helpers (sm_80+). Called convergently by full warps only.
// ---------------------------------------------------------------------------
__device__ __forceinline__ unsigned redux_max_u32(unsigned v) {
    unsigned r;
    asm volatile("redux.sync.max.u32 %0, %1, 0xffffffff;" : "=r"(r) : "r"(v));
    return r;
}
__device__ __forceinline__ int redux_min_s32(int v) {
    int r;
    asm volatile("redux.sync.min.s32 %0, %1, 0xffffffff;" : "=r"(r) : "r"(v));
    return r;
}

// ---------------------------------------------------------------------------
// Packed f32x2 helpers (Blackwell). Each half rounds with .rn — bit-identical
// to the scalar op on that half, so FPS distance math stays bit-exact.
// ---------------------------------------------------------------------------
__device__ __forceinline__ u64 pk2(float lo, float hi) {
    u64 r; asm("mov.b64 %0, {%1, %2};" : "=l"(r) : "f"(lo), "f"(hi)); return r;
}
__device__ __forceinline__ float2 upk2(u64 v) {
    float lo, hi; asm("mov.b64 {%0, %1}, %2;" : "=f"(lo), "=f"(hi) : "l"(v));
    return make_float2(lo, hi);
}
__device__ __forceinline__ u64 addx2(u64 a, u64 b) {
    u64 r; asm("add.rn.f32x2 %0, %1, %2;" : "=l"(r) : "l"(a), "l"(b)); return r;
}
__device__ __forceinline__ u64 mulx2(u64 a, u64 b) {
    u64 r; asm("mul.rn.f32x2 %0, %1, %2;" : "=l"(r) : "l"(a), "l"(b)); return r;
}

// ---------------------------------------------------------------------------
// Kernel 0: Morton-grid counting sort, one block per batch.
// 16^3 cells over [-5,5]^3 (clamped; inputs are standard normal). Order
// within a cell is atomic-nondeterministic — harmless: skips below are exact
// no-ops, so the FPS trajectory (hence the output) is order-independent.
// ---------------------------------------------------------------------------
__global__ __launch_bounds__(1024, 1)
void sort_kernel(const float* __restrict__ xyz) {
    const int b = blockIdx.x;
    const int t = threadIdx.x;
    const float* X = xyz + (size_t)b * NPTS * 3;

    __shared__ unsigned hist[4096];
    __shared__ unsigned warpsum[32];

#pragma unroll
    for (int c = t; c < 4096; c += 1024) hist[c] = 0;
    __syncthreads();

    unsigned cell[8];
#pragma unroll
    for (int j = 0; j < 8; j++) {
        const int i = t + j * 1024;
        const float x = X[3 * i + 0];
        const float y = X[3 * i + 1];
        const float z = X[3 * i + 2];
        const int ix = (int)fminf(fmaxf((x + 5.0f) * 1.6f, 0.0f), 15.0f);
        const int iy = (int)fminf(fmaxf((y + 5.0f) * 1.6f, 0.0f), 15.0f);
        const int iz = (int)fminf(fmaxf((z + 5.0f) * 1.6f, 0.0f), 15.0f);
        cell[j] = (unsigned)MORT4[ix] | ((unsigned)MORT4[iy] << 1)
                | ((unsigned)MORT4[iz] << 2);
        atomicAdd(&hist[cell[j]], 1u);
    }
    __syncthreads();

    // Block exclusive scan over 4096 counts; each thread owns 4 cells.
    const unsigned h0 = hist[4 * t + 0];
    const unsigned h1 = hist[4 * t + 1];
    const unsigned h2 = hist[4 * t + 2];
    const unsigned h3 = hist[4 * t + 3];
    const unsigned local = h0 + h1 + h2 + h3;
    unsigned inc = local;
#pragma unroll
    for (int o = 1; o < 32; o <<= 1) {
        const unsigned v = __shfl_up_sync(0xffffffff, inc, o);
        if ((t & 31) >= o) inc += v;
    }
    if ((t & 31) == 31) warpsum[t >> 5] = inc;
    __syncthreads();
    if (t < 32) {
        const unsigned v = warpsum[t];
        unsigned i2 = v;
#pragma unroll
        for (int o = 1; o < 32; o <<= 1) {
            const unsigned u = __shfl_up_sync(0xffffffff, i2, o);
            if (t >= o) i2 += u;
        }
        warpsum[t] = i2 - v;   // exclusive
    }
    __syncthreads();
    const unsigned excl = warpsum[t >> 5] + inc - local;
    hist[4 * t + 0] = excl;
    hist[4 * t + 1] = excl + h0;
    hist[4 * t + 2] = excl + h0 + h1;
    hist[4 * t + 3] = excl + h0 + h1 + h2;
    __syncthreads();

    const int base = b * NPTS;
#pragma unroll
    for (int j = 0; j < 8; j++) {
        const int i = t + j * 1024;
        const unsigned pos = atomicAdd(&hist[cell[j]], 1u);
        d_sx[base + pos] = X[3 * i + 0];
        d_sy[base + pos] = X[3 * i + 1];
        d_sz[base + pos] = X[3 * i + 2];
        d_sorig[base + pos] = i;
    }
}

// ---------------------------------------------------------------------------
// Kernel 1: FPS with exact warp-level pruning. One block per batch, 1024
// threads, 8 *contiguous sorted* points per thread. Each warp owns a compact
// 256-point region with an AABB held in registers (identical in every lane).
//
// Per iteration: if the conservative lower bound L on d2(any point in warp,
// center) satisfies L*0.999 >= warp's current max dist, then
// fminf(dist, d2) == dist for every point in the warp — the update is a
// bit-exact no-op, and the cached (max, argmin-orig-idx) stays valid.
// Active warps run the packed-f32x2 update (no FMA contraction; same
// association as the reference) and refresh their cache.
// ---------------------------------------------------------------------------
__global__ __launch_bounds__(1024, 1)
void fps_kernel(const float* __restrict__ xyz, float* __restrict__ new_xyz) {
    const int b = blockIdx.x;
    const int t = threadIdx.x;
    const int lane = t & 31;
    const int w = t >> 5;
    const float* X = xyz + (size_t)b * NPTS * 3;
    float* O = new_xyz + (size_t)b * NPOINT * 3;
    const int base = b * NPTS + t * 8;

    u64 pxp[4], pyp[4], pzp[4];
    float dist[8];
    int oidx[8];
    float alx = 1e38f, aly = 1e38f, alz = 1e38f;     // AABB lo
    float ahx = -1e38f, ahy = -1e38f, ahz = -1e38f;  // AABB hi
#pragma unroll
    for (int q = 0; q < 4; q++) {
        const float x0 = d_sx[base + 2 * q],     x1 = d_sx[base + 2 * q + 1];
        const float y0 = d_sy[base + 2 * q],     y1 = d_sy[base + 2 * q + 1];
        const float z0 = d_sz[base + 2 * q],     z1 = d_sz[base + 2 * q + 1];
        pxp[q] = pk2(x0, x1); pyp[q] = pk2(y0, y1); pzp[q] = pk2(z0, z1);
        oidx[2 * q]     = d_sorig[base + 2 * q];
        oidx[2 * q + 1] = d_sorig[base + 2 * q + 1];
        alx = fminf(alx, fminf(x0, x1)); ahx = fmaxf(ahx, fmaxf(x0, x1));
        aly = fminf(aly, fminf(y0, y1)); ahy = fmaxf(ahy, fmaxf(y0, y1));
        alz = fminf(alz, fminf(z0, z1)); ahz = fmaxf(ahz, fmaxf(z0, z1));
        dist[2 * q] = 1e38f; dist[2 * q + 1] = 1e38f;
    }
    // Warp AABB (identical in every lane afterwards).
#pragma unroll
    for (int o = 16; o > 0; o >>= 1) {
        alx = fminf(alx, __shfl_xor_sync(0xffffffff, alx, o));
        aly = fminf(aly, __shfl_xor_sync(0xffffffff, aly, o));
        alz = fminf(alz, __shfl_xor_sync(0xffffffff, alz, o));
        ahx = fmaxf(ahx, __shfl_xor_sync(0xffffffff, ahx, o));
        ahy = fmaxf(ahy, __shfl_xor_sync(0xffffffff, ahy, o));
        ahz = fmaxf(ahz, __shfl_xor_sync(0xffffffff, ahz, o));
    }

    __shared__ unsigned s_wv[32];
    __shared__ int      s_wi[32];
    __shared__ int      s_widx;

    float lx = X[0], ly = X[1], lz = X[2];   // first center = point 0
    if (t == 0) { O[0] = lx; O[1] = ly; O[2] = lz; }

    unsigned wbest = 0x7f7fffffu;   // FLT_MAX bits: forces update in iter 1
    int wbidx = 0;

    for (int k = 1; k < NPOINT; k++) {
        // Conservative lower bound on d2 from center to warp AABB.
        const float bx = fmaxf(fmaxf(alx - lx, lx - ahx), 0.0f);
        const float by = fmaxf(fmaxf(aly - ly, ly - ahy), 0.0f);
        const float bz = fmaxf(fmaxf(alz - lz, lz - ahz), 0.0f);
        const float L = bx * bx + by * by + bz * bz;
        const bool active = (L * 0.999f) < __uint_as_float(wbest);  // uniform

        if (active) {
            const unsigned nbx = __float_as_uint(lx) ^ 0x80000000u;
            const unsigned nby = __float_as_uint(ly) ^ 0x80000000u;
            const unsigned nbz = __float_as_uint(lz) ^ 0x80000000u;
            const u64 nlx2 = pk2(__uint_as_float(nbx), __uint_as_float(nbx));
            const u64 nly2 = pk2(__uint_as_float(nby), __uint_as_float(nby));
            const u64 nlz2 = pk2(__uint_as_float(nbz), __uint_as_float(nbz));
#pragma unroll
            for (int q = 0; q < 4; q++) {
                const u64 dx = addx2(pxp[q], nlx2);
                const u64 dy = addx2(pyp[q], nly2);
                const u64 dz = addx2(pzp[q], nlz2);
                // ((dx^2 + dy^2) + dz^2) — same association as reference.
                const u64 s = addx2(addx2(mulx2(dx, dx), mulx2(dy, dy)),
                                    mulx2(dz, dz));
                const float2 d2 = upk2(s);
                dist[2 * q]     = fminf(dist[2 * q],     d2.x);
                dist[2 * q + 1] = fminf(dist[2 * q + 1], d2.y);
            }
            const float m01 = fmaxf(dist[0], dist[1]);
            const float m23 = fmaxf(dist[2], dist[3]);
            const float m45 = fmaxf(dist[4], dist[5]);
            const float m67 = fmaxf(dist[6], dist[7]);
            const float best = fmaxf(fmaxf(m01, m23), fmaxf(m45, m67));

            // Warp argmax; ties -> min ORIGINAL index (jnp.argmax semantics).
            const unsigned vb = __float_as_uint(best);
            const unsigned wmax = redux_max_u32(vb);
            int cand = 0x7fffffff;
            if (vb == wmax) {
#pragma unroll
                for (int j = 0; j < 8; j++)
                    if (__float_as_uint(dist[j]) == wmax)
                        cand = min(cand, oidx[j]);
            }
            const int wimin = redux_min_s32(cand);
            wbest = wmax;
            wbidx = wimin;
        }
        if (lane == 0) { s_wv[w] = wbest; s_wi[w] = wbidx; }
        __syncthreads();

        if (t < 32) {
            const unsigned v2 = s_wv[t];
            const int      i2 = s_wi[t];
            const unsigned m2 = redux_max_u32(v2);
            const int c2 = (v2 == m2) ? i2 : 0x7fffffff;
            const int w2 = redux_min_s32(c2);
            if (t == 0) s_widx = w2;
        }
        __syncthreads();

        const int wi = s_widx;
        lx = __ldg(X + 3 * wi + 0);
        ly = __ldg(X + 3 * wi + 1);
        lz = __ldg(X + 3 * wi + 2);
        if (t == 0) { O[3 * k] = lx; O[3 * k + 1] = ly; O[3 * k + 2] = lz; }
    }
}

// ---------------------------------------------------------------------------
// Kernel 2: fused ball query + grouping (unchanged from round 2; 127us).
// ---------------------------------------------------------------------------
__global__ __launch_bounds__(256)
void ballgroup_kernel(const float* __restrict__ xyz,
                      const float* __restrict__ points,
                      const float* __restrict__ new_xyz,
                      float* __restrict__ new_points) {
    const int gwarp = (blockIdx.x * blockDim.x + threadIdx.x) >> 5;
    const int lane  = threadIdx.x & 31;
    const int wslot = threadIdx.x >> 5;
    if (gwarp >= BATCH * NPOINT) return;

    const int b = gwarp / NPOINT;
    const int p = gwarp % NPOINT;

    const float* X   = xyz    + (size_t)b * NPTS * 3;
    const float* P   = points + (size_t)b * NPTS * CFEAT;
    const float* ctr = new_xyz + (size_t)(b * NPOINT + p) * 3;
    const float cx = ctr[0], cy = ctr[1], cz = ctr[2];

    __shared__ int sidx[8][NSAMPLE];

    int cnt = 0;
    for (int base = 0; base < NPTS && cnt < NSAMPLE; base += 32) {
        const int i = base + lane;
        const float dx = X[3 * i + 0] - cx;
        const float dy = X[3 * i + 1] - cy;
        const float dz = X[3 * i + 2] - cz;
        const float d2 = __fadd_rn(__fadd_rn(__fmul_rn(dx, dx),
                                             __fmul_rn(dy, dy)),
                                   __fmul_rn(dz, dz));
        const bool in = d2 < R2;
        const unsigned m = __ballot_sync(0xffffffff, in);
        const int pos = cnt + __popc(m & ((1u << lane) - 1u));
        if (in && pos < NSAMPLE) sidx[wslot][pos] = i;
        cnt += __popc(m);
    }
    __syncwarp();

    const int nvalid = cnt < NSAMPLE ? cnt : NSAMPLE;
    const int first  = sidx[wslot][0];
    const int myidx  = (lane < nvalid) ? sidx[wslot][lane] : first;
    sidx[wslot][lane] = myidx;
    __syncwarp();

    float* OUT = new_points + (size_t)(b * NPOINT + p) * NSAMPLE * OUTC;
    const float cc = (lane == 0) ? cx : ((lane == 1) ? cy : cz);

#pragma unroll
    for (int s0 = 0; s0 < NSAMPLE; s0 += 4) {
        int id[4];
#pragma unroll
        for (int u = 0; u < 4; u++) id[u] = sidx[wslot][s0 + u];
#pragma unroll
        for (int u = 0; u < 4; u++) {
            const int idx = id[u];
            float v;
            if (lane < 3) {
                v = X[3 * idx + lane] - cc;
            } else {
                v = P[(size_t)idx * CFEAT + (lane - 3)];
            }
            OUT[(s0 + u) * OUTC + lane] = v;
            if (lane < 3) {
                OUT[(s0 + u) * OUTC + 32 + lane] =
                    P[(size_t)idx * CFEAT + 29 + lane];
            }
        }
    }
}

// ---------------------------------------------------------------------------
// Launch: d_in[0] = xyz (8*8192*3 f32), d_in[1] = points (8*8192*32 f32).
// d_out = [ new_xyz : 8*1024*3 ][ new_points : 8*1024*32*35 ] f32.
// ---------------------------------------------------------------------------
extern "C" void kernel_launch(void* const* d_in, const int* in_sizes, int n_in,
                              void* d_out, int out_size) {
    const float* xyz    = (const float*)d_in[0];
    const float* points = (const float*)d_in[1];
    float* new_xyz    = (float*)d_out;
    float* new_points = new_xyz + (size_t)BATCH * NPOINT * 3;

    sort_kernel<<<BATCH, 1024>>>(xyz);
    fps_kernel<<<BATCH, 1024>>>(xyz, new_xyz);

    const int nwarps  = BATCH * NPOINT;
    const int threads = 256;
    const int blocks  = (nwarps * 32) / threads;
    ballgroup_kernel<<<blocks, threads>>>(xyz, points, new_xyz, new_points);
}